// round 14
// baseline (speedup 1.0000x reference)
#include <cuda_runtime.h>
#include <cuda_bf16.h>
#include <cstdint>

// Problem constants
#define PB   64       // batch (cells)
#define PT   64       // num TFs
#define PP   21000    // total peaks
#define PG   2000     // genes
#define PH   3000     // NUM_GOS*GO_DIM
#define PNO  7        // n_out

// d_out layout: x_cat [64*2000] | h [64*3000] | out [64*7]
#define OFF_XCAT 0
#define OFF_H    (PB*PG)
#define OFF_OUT  (PB*PG + PB*PH)

#define G1_NSPLIT 6      // measured best (R8); 12 regressed (R10)

// scratch (device globals — no allocation allowed).
// RULES learned this session:
//  * R4-R7: NEVER pass these as kernel args from host code — host shadow
//    symbol + GB300 ATS silently reads zero-filled host copy. Device-side
//    references only.
//  * R4, R12: any smem array accessed via float4 MUST have row stride
//    divisible by 4 floats (16 B), or LDS.128/STS.128 traps "misaligned".
__device__ float g_xcat_pre[PB*PG];              // segment sums, pre-bias
__device__ float g_At[PG*PB];                    // x_cat transposed [k=2000][m=64]
__device__ float g_hpre[G1_NSPLIT*PB*PH];        // GEMM1 k-split slabs

// ---------------------------------------------------------------------------
// init: zero the atomic accumulator
// ---------------------------------------------------------------------------
__global__ void init_kernel() {
    int i = blockIdx.x * blockDim.x + threadIdx.x;
    if (i < PB*PG) g_xcat_pre[i] = 0.0f;
}

// ---------------------------------------------------------------------------
// Kernel 1: per-peak dot over TFs + ragged per-gene reduction.
//   grid = (55, 8) = 440 blocks (~3/SM, 97% balanced), block = 96 threads.
//   Each thread owns 4 CONSECUTIVE peaks -> x read via LDG.128 (float4),
//   perfectly coalesced 512B per warp. W staged transposed in 32-TF chunks.
// ---------------------------------------------------------------------------
#define PK_TPB 96        // threads per block
#define PK_PC  384       // peaks per block (96 * 4)
#define PK_BG  8         // batch rows per block
#define PK_TCH 32        // TFs staged per chunk
#define PK_SUB 8         // TFs per inner sub-step (w registers)
#define WS_LD  388       // row pad; MULTIPLE OF 4 for float4 LDS alignment

__global__ __launch_bounds__(PK_TPB) void peak_kernel(
    const float* __restrict__ x,        // [B,T,P]
    const float* __restrict__ Wp,       // [P,T]
    const int*   __restrict__ gene_ids) // [P]
{
    __shared__ __align__(16) float Ws[PK_TCH][WS_LD];  // ~49.7 KB, [t_local][peak]
    __shared__ __align__(16) float vals[PK_PC];

    const int tid = threadIdx.x;
    const int p0  = blockIdx.x * PK_PC;
    const int b0  = blockIdx.y * PK_BG;
    const int p   = p0 + tid * 4;           // first of this thread's 4 peaks
    const bool valid = (p < PP);            // PP%4==0 -> all-or-nothing

    // gene run structure for my 4 peaks (leader = first peak of a run
    // within this block's chunk; block-boundary partials accumulate via atomics)
    int  gene[4];
    bool lead[4] = {false, false, false, false};
    int  rl[4]   = {0, 0, 0, 0};
    if (valid) {
        #pragma unroll
        for (int i = 0; i < 4; i++) {
            int pg = p + i;                 // global peak
            int pi = tid * 4 + i;           // local peak index
            gene[i] = gene_ids[pg];
            lead[i] = (pi == 0) || (gene_ids[pg - 1] != gene[i]);
            if (lead[i]) {
                int maxr = min(PK_PC - pi, PP - pg);
                int r = 1;
                while (r < maxr && gene_ids[pg + r] == gene[i]) r++;
                rl[i] = r;
            }
        }
    }

    float4 acc[PK_BG];
    #pragma unroll
    for (int bi = 0; bi < PK_BG; bi++) acc[bi] = make_float4(0.f, 0.f, 0.f, 0.f);

    for (int tc = 0; tc < PT; tc += PK_TCH) {
        // stage W chunk transposed: 384 rows x 8 quads = 3072 float4, 32/thread
        #pragma unroll
        for (int it = 0; it < 32; it++) {
            int q  = tid + it * PK_TPB;     // 0..3071
            int r  = q >> 3;                // peak row 0..383
            int cq = q & 7;                 // quad 0..7 within 32-t chunk
            if (p0 + r < PP) {
                float4 v = *(const float4*)(Wp + (long)(p0 + r) * PT + tc + cq * 4);
                Ws[cq*4+0][r] = v.x;
                Ws[cq*4+1][r] = v.y;
                Ws[cq*4+2][r] = v.z;
                Ws[cq*4+3][r] = v.w;
            }
        }
        __syncthreads();

        if (valid) {
            #pragma unroll
            for (int sub = 0; sub < PK_TCH; sub += PK_SUB) {
                // w[i] = W for (t = tc+sub+i, my 4 peaks)
                float4 w[PK_SUB];
                #pragma unroll
                for (int i = 0; i < PK_SUB; i++)
                    w[i] = *(const float4*)&Ws[sub + i][tid * 4];

                const float* xb = x + (long)(tc + sub) * PP + p;
                #pragma unroll
                for (int bi = 0; bi < PK_BG; bi++) {
                    const float* xr = xb + (long)(b0 + bi) * PT * PP;
                    float4 a = acc[bi];
                    #pragma unroll
                    for (int i = 0; i < PK_SUB; i++) {   // 8 indep LDG.128
                        float4 xv = *(const float4*)(xr + (long)i * PP);
                        a.x += xv.x * w[i].x;
                        a.y += xv.y * w[i].y;
                        a.z += xv.z * w[i].z;
                        a.w += xv.w * w[i].w;
                    }
                    acc[bi] = a;
                }
            }
        }
        __syncthreads();
    }

    // segmented reduction + one atomic per gene-run per b
    for (int bi = 0; bi < PK_BG; bi++) {
        if (valid) *(float4*)&vals[tid * 4] = acc[bi];
        __syncthreads();
        if (valid) {
            #pragma unroll
            for (int i = 0; i < 4; i++) {
                if (lead[i]) {
                    int pi = tid * 4 + i;
                    float s = 0.0f;
                    for (int r = 0; r < rl[i]; r++) s += vals[pi + r];
                    atomicAdd(&g_xcat_pre[(b0 + bi) * PG + gene[i]], s);
                }
            }
        }
        __syncthreads();
    }
}

// ---------------------------------------------------------------------------
// x_cat = relu(pre + b_genes) -> d_out AND transposed copy for GEMM1
// ---------------------------------------------------------------------------
__global__ void xcat_kernel(const float* __restrict__ b_genes, float* __restrict__ out)
{
    int i = blockIdx.x * blockDim.x + threadIdx.x;
    if (i < PB*PG) {
        int m = i / PG, g = i % PG;
        float v = fmaxf(g_xcat_pre[i] + b_genes[g], 0.0f);
        out[OFF_XCAT + i] = v;
        g_At[g * PB + m]  = v;
    }
}

// ---------------------------------------------------------------------------
// GEMM1 (R8 config — measured 92% of FFMA floor): slab = At^T @ W1 slice
//   grid = (24, 6), block = 256. Block tile 64x128, KC=16, thread tile 4x8.
// ---------------------------------------------------------------------------
#define G1_KC 16
#define G1_NT 128

__global__ __launch_bounds__(256) void gemm1_kernel(
    const float* __restrict__ W1)       // [2000][3000]
{
    __shared__ __align__(16) float As[G1_KC][PB];     // 4 KB
    __shared__ __align__(16) float Bs[G1_KC][G1_NT];  // 8 KB

    const float* At = g_At;             // device-side symbol reference

    const int tid = threadIdx.x;
    const int tx = tid & 15;
    const int ty = tid >> 4;
    const int jt = blockIdx.x * G1_NT;
    const int split = blockIdx.y;
    const int kbase = split * 336;                  // 5x336 + 320 = 2000
    const int kc = min(336, PG - kbase);
    const int ntiles = kc / G1_KC;                  // 21 or 20

    const int a_kk = tid >> 4;
    const int a_m  = (tid & 15) * 4;
    const int b_kk = tid >> 5;
    const int b_j  = (tid & 31) * 4;
    const bool b_ok = (jt + b_j + 4 <= PH);

    float4 aReg, bReg0, bReg1;
    auto fetch = [&](int kt) {
        int k0 = kbase + kt * G1_KC;
        aReg = *(const float4*)(At + (long)(k0 + a_kk) * PB + a_m);
        if (b_ok) {
            bReg0 = *(const float4*)(W1 + (long)(k0 + b_kk)     * PH + jt + b_j);
            bReg1 = *(const float4*)(W1 + (long)(k0 + 8 + b_kk) * PH + jt + b_j);
        } else {
            bReg0 = make_float4(0.f, 0.f, 0.f, 0.f);
            bReg1 = make_float4(0.f, 0.f, 0.f, 0.f);
        }
    };

    float acc[4][8];
    #pragma unroll
    for (int mm = 0; mm < 4; mm++)
        #pragma unroll
        for (int c = 0; c < 8; c++) acc[mm][c] = 0.0f;

    fetch(0);

    for (int kt = 0; kt < ntiles; kt++) {
        *(float4*)&As[a_kk][a_m]       = aReg;
        *(float4*)&Bs[b_kk][b_j]       = bReg0;
        *(float4*)&Bs[8 + b_kk][b_j]   = bReg1;
        __syncthreads();

        if (kt + 1 < ntiles) fetch(kt + 1);

        #pragma unroll
        for (int kk = 0; kk < G1_KC; kk++) {
            float4 a  = *(const float4*)&As[kk][ty * 4];
            float4 bl = *(const float4*)&Bs[kk][tx * 4];
            float4 bh = *(const float4*)&Bs[kk][64 + tx * 4];
            float am[4] = {a.x, a.y, a.z, a.w};
            float bj[8] = {bl.x, bl.y, bl.z, bl.w, bh.x, bh.y, bh.z, bh.w};
            #pragma unroll
            for (int mm = 0; mm < 4; mm++)
                #pragma unroll
                for (int c = 0; c < 8; c++)
                    acc[mm][c] += am[mm] * bj[c];
        }
        __syncthreads();
    }

    float* slab = g_hpre + (long)split * PB * PH;
    #pragma unroll
    for (int mm = 0; mm < 4; mm++) {
        int m = ty * 4 + mm;
        int j0 = jt + tx * 4;
        if (j0 + 4 <= PH)
            *(float4*)&slab[(long)m * PH + j0] =
                make_float4(acc[mm][0], acc[mm][1], acc[mm][2], acc[mm][3]);
        int j1 = jt + 64 + tx * 4;
        if (j1 + 4 <= PH)
            *(float4*)&slab[(long)m * PH + j1] =
                make_float4(acc[mm][4], acc[mm][5], acc[mm][6], acc[mm][7]);
    }
}

// ---------------------------------------------------------------------------
// Fused tail: h = relu(sum_slabs + b1) -> d_out[OFF_H:], and
//             out[b,:] = h[b,:] @ W2 + b2 -> d_out[OFF_OUT:].
// ---------------------------------------------------------------------------
__global__ __launch_bounds__(512) void tail_kernel(
    const float* __restrict__ b1,
    const float* __restrict__ W2,       // [3000,7]
    const float* __restrict__ b2,
    float* __restrict__ out)            // full d_out base
{
    const int b = blockIdx.x;
    const int tid = threadIdx.x;
    float acc[PNO] = {};

    for (int k = tid; k < PH; k += 512) {
        float v = b1[k];
        #pragma unroll
        for (int s = 0; s < G1_NSPLIT; s++)
            v += g_hpre[(long)s * (PB*PH) + b * PH + k];
        v = fmaxf(v, 0.0f);
        out[OFF_H + b * PH + k] = v;
        #pragma unroll
        for (int j = 0; j < PNO; j++) acc[j] += v * W2[k * PNO + j];
    }

    #pragma unroll
    for (int j = 0; j < PNO; j++)
        #pragma unroll
        for (int off = 16; off > 0; off >>= 1)
            acc[j] += __shfl_down_sync(0xFFFFFFFFu, acc[j], off);

    __shared__ float red[16][PNO];
    int wid = tid >> 5, lid = tid & 31;
    if (lid == 0)
        for (int j = 0; j < PNO; j++) red[wid][j] = acc[j];
    __syncthreads();
    if (tid < PNO) {
        float s = b2[tid];
        #pragma unroll
        for (int w = 0; w < 16; w++) s += red[w][tid];
        out[OFF_OUT + b * PNO + tid] = s;
    }
}

// ---------------------------------------------------------------------------
extern "C" void kernel_launch(void* const* d_in, const int* in_sizes, int n_in,
                              void* d_out, int out_size)
{
    const float* x        = (const float*)d_in[0]; // [64,64,21000]
    const float* W_peaks  = (const float*)d_in[1]; // [21000,64]
    const float* b_genes  = (const float*)d_in[2]; // [2000]
    const float* W1       = (const float*)d_in[3]; // [2000,3000]
    const float* b1       = (const float*)d_in[4]; // [3000]
    const float* W2       = (const float*)d_in[5]; // [3000,7]
    const float* b2       = (const float*)d_in[6]; // [7]
    const int*   gene_ids = (const int*)  d_in[7]; // [21000]
    float* out = (float*)d_out;

    // 1. zero the atomic accumulator
    init_kernel<<<(PB*PG + 255) / 256, 256>>>();

    // 2. peak dot + segment sum (float4 x loads, 440 balanced blocks)
    dim3 pk_grid((PP + PK_PC - 1) / PK_PC, PB / PK_BG);   // (55, 8)
    peak_kernel<<<pk_grid, PK_TPB>>>(x, W_peaks, gene_ids);

    // 3. x_cat finalize -> d_out + transposed copy (device global, written on device)
    xcat_kernel<<<(PB*PG + 255) / 256, 256>>>(b_genes, out);

    // 4. GEMM1 (k-split slabs, no atomics; A referenced via device symbol)
    dim3 g1_grid((PH + G1_NT - 1) / G1_NT, G1_NSPLIT);    // (24, 6)
    gemm1_kernel<<<g1_grid, 256>>>(W1);

    // 5. fused h finalize + GEMM2 -> d_out
    tail_kernel<<<PB, 512>>>(b1, W2, b2, out);
}

// round 15
// speedup vs baseline: 1.7137x; 1.7137x over previous
#include <cuda_runtime.h>
#include <cuda_bf16.h>
#include <cstdint>

// Problem constants
#define PB   64       // batch (cells)
#define PT   64       // num TFs
#define PP   21000    // total peaks
#define PG   2000     // genes
#define PH   3000     // NUM_GOS*GO_DIM
#define PNO  7        // n_out

// d_out layout: x_cat [64*2000] | h [64*3000] | out [64*7]
#define OFF_XCAT 0
#define OFF_H    (PB*PG)
#define OFF_OUT  (PB*PG + PB*PH)

#define G1_NSPLIT 6      // measured best (R8); 12 regressed (R10)

// scratch (device globals — no allocation allowed).
// RULES learned this session:
//  * R4-R7: NEVER pass these as kernel args from host code — host shadow
//    symbol + GB300 ATS silently reads zero-filled host copy. Device-side
//    references only.
//  * R4, R12: any smem array accessed via float4 MUST have row stride
//    divisible by 4 floats (16 B), or LDS.128/STS.128 traps "misaligned".
//  * R14: peak kernel is occupancy-bound, not LDG-issue-bound — scalar
//    1-line-per-warp loads at ~24 warps/SM beat float4 at 12 warps/SM 2x.
__device__ float g_xcat_pre[PB*PG];              // segment sums, pre-bias
__device__ float g_At[PG*PB];                    // x_cat transposed [k=2000][m=64]
__device__ float g_hpre[G1_NSPLIT*PB*PH];        // GEMM1 k-split slabs

// ---------------------------------------------------------------------------
// init: zero the atomic accumulator
// ---------------------------------------------------------------------------
__global__ void init_kernel() {
    int i = blockIdx.x * blockDim.x + threadIdx.x;
    if (i < PB*PG) g_xcat_pre[i] = 0.0f;
}

// ---------------------------------------------------------------------------
// Kernel 1 (R11 config + single-sync epilogue): per-peak dot over TFs +
//   ragged per-gene reduction. grid = (165, 8), block = 128.
//   Each block: 128 peaks x 8 batch rows, 64-TF loop in 32-TF chunks.
// ---------------------------------------------------------------------------
#define PK_PC 128
#define PK_BG 8
#define PK_TCH 32
#define WS_LD 129   // pad: conflict-free STS+LDS (scalar access, any pad ok)
#define VL_LD 132   // vals row stride (scalar access)

__global__ __launch_bounds__(PK_PC) void peak_kernel(
    const float* __restrict__ x,        // [B,T,P]
    const float* __restrict__ Wp,       // [P,T]
    const int*   __restrict__ gene_ids) // [P]
{
    __shared__ float Ws[PK_TCH * WS_LD];    // 16.5 KB, [t_local][peak]
    __shared__ float vals[PK_BG][VL_LD];    // 4.2 KB, all 8 b-rows at once

    const int tid = threadIdx.x;
    const int p0  = blockIdx.x * PK_PC;
    const int b0  = blockIdx.y * PK_BG;
    const int p   = p0 + tid;
    const bool valid = (p < PP);

    // gene run structure (leader = first peak of a gene within this chunk)
    int g = 0, runlen = 0;
    bool leader = false;
    if (valid) {
        g = gene_ids[p];
        leader = (tid == 0) || (gene_ids[p-1] != g);
        if (leader) {
            int maxr = min(PK_PC - tid, PP - p);
            runlen = 1;
            while (runlen < maxr && gene_ids[p + runlen] == g) runlen++;
        }
    }

    float acc[PK_BG];
    #pragma unroll
    for (int bi = 0; bi < PK_BG; bi++) acc[bi] = 0.0f;

    for (int tc = 0; tc < PT; tc += PK_TCH) {
        // stage W chunk [tc, tc+32) transposed. 1024 float4 loads, 8/thread.
        #pragma unroll
        for (int it = 0; it < 8; it++) {
            int q  = tid + it * PK_PC;
            int r  = q >> 3;             // peak row 0..127
            int cq = q & 7;              // quad 0..7 within 32-t chunk
            if (p0 + r < PP) {
                float4 v = *(const float4*)(Wp + (long)(p0 + r) * PT + tc + cq * 4);
                Ws[(cq*4+0) * WS_LD + r] = v.x;
                Ws[(cq*4+1) * WS_LD + r] = v.y;
                Ws[(cq*4+2) * WS_LD + r] = v.z;
                Ws[(cq*4+3) * WS_LD + r] = v.w;
            }
        }
        __syncthreads();

        if (valid) {
            #pragma unroll
            for (int sub = 0; sub < PK_TCH; sub += 16) {
                float w[16];
                #pragma unroll
                for (int i = 0; i < 16; i++) w[i] = Ws[(sub + i) * WS_LD + tid];
                const float* xb = x + (long)(tc + sub) * PP + p;
                #pragma unroll
                for (int bi = 0; bi < PK_BG; bi++) {
                    const float* xr = xb + (long)(b0 + bi) * PT * PP;
                    float s = 0.0f;
                    #pragma unroll
                    for (int i = 0; i < 16; i++)      // MLP = 16
                        s += xr[(long)i * PP] * w[i];
                    acc[bi] += s;
                }
            }
        }
        __syncthreads();
    }

    // single-sync segmented epilogue: store all 8 b-rows, one barrier,
    // leaders scan their run for every b (cross-bi ILP, 1 sync vs 16).
    #pragma unroll
    for (int bi = 0; bi < PK_BG; bi++)
        vals[bi][tid] = valid ? acc[bi] : 0.0f;
    __syncthreads();
    if (leader) {
        #pragma unroll 1
        for (int bi = 0; bi < PK_BG; bi++) {
            float s = 0.0f;
            for (int r = 0; r < runlen; r++) s += vals[bi][tid + r];
            atomicAdd(&g_xcat_pre[(b0 + bi) * PG + g], s);
        }
    }
}

// ---------------------------------------------------------------------------
// x_cat = relu(pre + b_genes) -> d_out AND transposed copy for GEMM1
// ---------------------------------------------------------------------------
__global__ void xcat_kernel(const float* __restrict__ b_genes, float* __restrict__ out)
{
    int i = blockIdx.x * blockDim.x + threadIdx.x;
    if (i < PB*PG) {
        int m = i / PG, g = i % PG;
        float v = fmaxf(g_xcat_pre[i] + b_genes[g], 0.0f);
        out[OFF_XCAT + i] = v;
        g_At[g * PB + m]  = v;
    }
}

// ---------------------------------------------------------------------------
// GEMM1 (R8 config — measured 92% of FFMA floor): slab = At^T @ W1 slice
//   grid = (24, 6), block = 256. Block tile 64x128, KC=16, thread tile 4x8.
// ---------------------------------------------------------------------------
#define G1_KC 16
#define G1_NT 128

__global__ __launch_bounds__(256) void gemm1_kernel(
    const float* __restrict__ W1)       // [2000][3000]
{
    __shared__ __align__(16) float As[G1_KC][PB];     // 4 KB
    __shared__ __align__(16) float Bs[G1_KC][G1_NT];  // 8 KB

    const float* At = g_At;             // device-side symbol reference

    const int tid = threadIdx.x;
    const int tx = tid & 15;
    const int ty = tid >> 4;
    const int jt = blockIdx.x * G1_NT;
    const int split = blockIdx.y;
    const int kbase = split * 336;                  // 5x336 + 320 = 2000
    const int kc = min(336, PG - kbase);
    const int ntiles = kc / G1_KC;                  // 21 or 20

    const int a_kk = tid >> 4;
    const int a_m  = (tid & 15) * 4;
    const int b_kk = tid >> 5;
    const int b_j  = (tid & 31) * 4;
    const bool b_ok = (jt + b_j + 4 <= PH);

    float4 aReg, bReg0, bReg1;
    auto fetch = [&](int kt) {
        int k0 = kbase + kt * G1_KC;
        aReg = *(const float4*)(At + (long)(k0 + a_kk) * PB + a_m);
        if (b_ok) {
            bReg0 = *(const float4*)(W1 + (long)(k0 + b_kk)     * PH + jt + b_j);
            bReg1 = *(const float4*)(W1 + (long)(k0 + 8 + b_kk) * PH + jt + b_j);
        } else {
            bReg0 = make_float4(0.f, 0.f, 0.f, 0.f);
            bReg1 = make_float4(0.f, 0.f, 0.f, 0.f);
        }
    };

    float acc[4][8];
    #pragma unroll
    for (int mm = 0; mm < 4; mm++)
        #pragma unroll
        for (int c = 0; c < 8; c++) acc[mm][c] = 0.0f;

    fetch(0);

    for (int kt = 0; kt < ntiles; kt++) {
        *(float4*)&As[a_kk][a_m]       = aReg;
        *(float4*)&Bs[b_kk][b_j]       = bReg0;
        *(float4*)&Bs[8 + b_kk][b_j]   = bReg1;
        __syncthreads();

        if (kt + 1 < ntiles) fetch(kt + 1);

        #pragma unroll
        for (int kk = 0; kk < G1_KC; kk++) {
            float4 a  = *(const float4*)&As[kk][ty * 4];
            float4 bl = *(const float4*)&Bs[kk][tx * 4];
            float4 bh = *(const float4*)&Bs[kk][64 + tx * 4];
            float am[4] = {a.x, a.y, a.z, a.w};
            float bj[8] = {bl.x, bl.y, bl.z, bl.w, bh.x, bh.y, bh.z, bh.w};
            #pragma unroll
            for (int mm = 0; mm < 4; mm++)
                #pragma unroll
                for (int c = 0; c < 8; c++)
                    acc[mm][c] += am[mm] * bj[c];
        }
        __syncthreads();
    }

    float* slab = g_hpre + (long)split * PB * PH;
    #pragma unroll
    for (int mm = 0; mm < 4; mm++) {
        int m = ty * 4 + mm;
        int j0 = jt + tx * 4;
        if (j0 + 4 <= PH)
            *(float4*)&slab[(long)m * PH + j0] =
                make_float4(acc[mm][0], acc[mm][1], acc[mm][2], acc[mm][3]);
        int j1 = jt + 64 + tx * 4;
        if (j1 + 4 <= PH)
            *(float4*)&slab[(long)m * PH + j1] =
                make_float4(acc[mm][4], acc[mm][5], acc[mm][6], acc[mm][7]);
    }
}

// ---------------------------------------------------------------------------
// Fused tail: h = relu(sum_slabs + b1) -> d_out[OFF_H:], and
//             out[b,:] = h[b,:] @ W2 + b2 -> d_out[OFF_OUT:].
// ---------------------------------------------------------------------------
__global__ __launch_bounds__(512) void tail_kernel(
    const float* __restrict__ b1,
    const float* __restrict__ W2,       // [3000,7]
    const float* __restrict__ b2,
    float* __restrict__ out)            // full d_out base
{
    const int b = blockIdx.x;
    const int tid = threadIdx.x;
    float acc[PNO] = {};

    for (int k = tid; k < PH; k += 512) {
        float v = b1[k];
        #pragma unroll
        for (int s = 0; s < G1_NSPLIT; s++)
            v += g_hpre[(long)s * (PB*PH) + b * PH + k];
        v = fmaxf(v, 0.0f);
        out[OFF_H + b * PH + k] = v;
        #pragma unroll
        for (int j = 0; j < PNO; j++) acc[j] += v * W2[k * PNO + j];
    }

    #pragma unroll
    for (int j = 0; j < PNO; j++)
        #pragma unroll
        for (int off = 16; off > 0; off >>= 1)
            acc[j] += __shfl_down_sync(0xFFFFFFFFu, acc[j], off);

    __shared__ float red[16][PNO];
    int wid = tid >> 5, lid = tid & 31;
    if (lid == 0)
        for (int j = 0; j < PNO; j++) red[wid][j] = acc[j];
    __syncthreads();
    if (tid < PNO) {
        float s = b2[tid];
        #pragma unroll
        for (int w = 0; w < 16; w++) s += red[w][tid];
        out[OFF_OUT + b * PNO + tid] = s;
    }
}

// ---------------------------------------------------------------------------
extern "C" void kernel_launch(void* const* d_in, const int* in_sizes, int n_in,
                              void* d_out, int out_size)
{
    const float* x        = (const float*)d_in[0]; // [64,64,21000]
    const float* W_peaks  = (const float*)d_in[1]; // [21000,64]
    const float* b_genes  = (const float*)d_in[2]; // [2000]
    const float* W1       = (const float*)d_in[3]; // [2000,3000]
    const float* b1       = (const float*)d_in[4]; // [3000]
    const float* W2       = (const float*)d_in[5]; // [3000,7]
    const float* b2       = (const float*)d_in[6]; // [7]
    const int*   gene_ids = (const int*)  d_in[7]; // [21000]
    float* out = (float*)d_out;

    // 1. zero the atomic accumulator
    init_kernel<<<(PB*PG + 255) / 256, 256>>>();

    // 2. peak dot + segment sum (R11 measured-best shape)
    dim3 pk_grid((PP + PK_PC - 1) / PK_PC, PB / PK_BG);   // (165, 8)
    peak_kernel<<<pk_grid, PK_PC>>>(x, W_peaks, gene_ids);

    // 3. x_cat finalize -> d_out + transposed copy (device global, written on device)
    xcat_kernel<<<(PB*PG + 255) / 256, 256>>>(b_genes, out);

    // 4. GEMM1 (k-split slabs, no atomics; A referenced via device symbol)
    dim3 g1_grid((PH + G1_NT - 1) / G1_NT, G1_NSPLIT);    // (24, 6)
    gemm1_kernel<<<g1_grid, 256>>>(W1);

    // 5. fused h finalize + GEMM2 -> d_out
    tail_kernel<<<PB, 512>>>(b1, W2, b2, out);
}